// round 7
// baseline (speedup 1.0000x reference)
#include <cuda_runtime.h>
#include <cuda_bf16.h>

#define NN 50000
#define NE 800000
#define IND 128
#define OUTD 64
#define HEADS 4
#define HD 256      // HEADS*OUTD
#define HID 256
#define MOUT 128

// ---- scratch (device globals: allocation-free) ----
__device__ float g_h[(size_t)NN * HD];        // per-head transformed features [N, H*D]
__device__ float g_num[(size_t)NN * HD];      // softmax numerator accum
__device__ float g_hidden[(size_t)NN * HID];  // MLP hidden
__device__ float g_s_src[NN * HEADS];
__device__ float g_s_dst[NN * HEADS];
__device__ float g_den[NN * HEADS];
__device__ float g_Wc[IND * HD];              // repacked W_n -> [IND, H*D]

// ---- pack W_n [H, IND, OUTD] -> Wc [IND, H*OUTD] ----
__global__ void pack_w_kernel(const float* __restrict__ Wn) {
    int i = blockIdx.x * blockDim.x + threadIdx.x;
    if (i < IND * HD) {
        int c = i / HD;
        int j = i % HD;
        int h = j >> 6;
        int d = j & 63;
        g_Wc[i] = Wn[h * (IND * OUTD) + c * OUTD + d];
    }
}

// ---- zero num + den ----
__global__ void zero_kernel() {
    int i = blockIdx.x * blockDim.x + threadIdx.x;
    if (i < NN * HD) g_num[i] = 0.0f;
    if (i < NN * HEADS) g_den[i] = 0.0f;
}

__device__ __forceinline__ unsigned f2tf32(float f) {
    unsigned r;
    asm("cvt.rna.tf32.f32 %0, %1;" : "=r"(r) : "f"(f));
    return r;
}

__device__ __forceinline__ void mma_tf32(float& c0, float& c1, float& c2, float& c3,
                                         unsigned a0, unsigned a1, unsigned a2, unsigned a3,
                                         unsigned b0, unsigned b1) {
    asm volatile("mma.sync.aligned.m16n8k8.row.col.f32.tf32.tf32.f32 "
                 "{%0,%1,%2,%3}, {%4,%5,%6,%7}, {%8,%9}, {%0,%1,%2,%3};"
                 : "+f"(c0), "+f"(c1), "+f"(c2), "+f"(c3)
                 : "r"(a0), "r"(a1), "r"(a2), "r"(a3), "r"(b0), "r"(b1));
}

// ---- tf32 tensor-core GEMM: C[M,N] = act(A' @ B + bias) ----
// BM=128, BN=128, BK=32, 256 threads (8 warps, 4x2 warp grid, each warp 32x64).
// AMODE 0: A plain. AMODE 1: A = relu(num/safe_den) on load (den per (row,head)).
// EPI   0: none. 1: +bias, relu. 2: +bias.
template<int AMODE, int EPI>
__global__ void __launch_bounds__(256)
gemm_tf32_kernel(const float* __restrict__ A, const float* __restrict__ B,
                 const float* __restrict__ bias, const float* __restrict__ den,
                 float* __restrict__ C, int M, int N, int K)
{
    const int BM = 128, BN = 128, BK = 32;
    const int APAD = 36;   // stride so A-frag LDS (4k' + m) is conflict-free
    const int BPAD = 136;  // stride so B-frag LDS (8k' + n) is conflict-free
    __shared__ unsigned As[BM * APAD];   // [m][k]
    __shared__ unsigned Bs[BK * BPAD];   // [k][n]

    int tid = threadIdx.x;
    int wid = tid >> 5;
    int lane = tid & 31;
    int grp = lane >> 2;        // 0..7
    int tig = lane & 3;         // 0..3

    int warp_m = (wid & 3) * 32;   // 4 warps along M
    int warp_n = (wid >> 2) * 64;  // 2 warps along N

    int m0 = blockIdx.x * BM;
    int n0 = blockIdx.y * BN;

    float acc[2][8][4];
#pragma unroll
    for (int i = 0; i < 2; i++)
#pragma unroll
        for (int j = 0; j < 8; j++)
#pragma unroll
            for (int q = 0; q < 4; q++) acc[i][j][q] = 0.0f;

    for (int k0 = 0; k0 < K; k0 += BK) {
        // --- load A tile 128x32 (1024 float4, 4 per thread) ---
#pragma unroll
        for (int j = 0; j < 4; j++) {
            int i = tid + j * 256;
            int row = i >> 3;           // /8 float4 per row
            int c4 = (i & 7) * 4;
            int gm = m0 + row;
            float4 v = make_float4(0.f, 0.f, 0.f, 0.f);
            if (gm < M) {
                v = *(const float4*)(A + (size_t)gm * K + k0 + c4);
                if (AMODE == 1) {
                    float dv = den[gm * HEADS + ((k0 + c4) >> 6)];
                    float inv = dv > 0.0f ? 1.0f / dv : 0.0f;
                    v.x = fmaxf(v.x * inv, 0.0f);
                    v.y = fmaxf(v.y * inv, 0.0f);
                    v.z = fmaxf(v.z * inv, 0.0f);
                    v.w = fmaxf(v.w * inv, 0.0f);
                }
            }
            unsigned* p = &As[row * APAD + c4];
            p[0] = f2tf32(v.x); p[1] = f2tf32(v.y);
            p[2] = f2tf32(v.z); p[3] = f2tf32(v.w);
        }
        // --- load B tile 32x128 (1024 float4, 4 per thread) ---
#pragma unroll
        for (int j = 0; j < 4; j++) {
            int i = tid + j * 256;
            int row = i >> 5;           // /32 float4 per row
            int c4 = (i & 31) * 4;
            float4 v = *(const float4*)(B + (size_t)(k0 + row) * N + n0 + c4);
            unsigned* p = &Bs[row * BPAD + c4];
            p[0] = f2tf32(v.x); p[1] = f2tf32(v.y);
            p[2] = f2tf32(v.z); p[3] = f2tf32(v.w);
        }
        __syncthreads();

#pragma unroll
        for (int kk = 0; kk < BK; kk += 8) {
            unsigned af[2][4];
#pragma unroll
            for (int mt = 0; mt < 2; mt++) {
                int r0 = warp_m + mt * 16 + grp;
                af[mt][0] = As[(r0)     * APAD + kk + tig];
                af[mt][1] = As[(r0 + 8) * APAD + kk + tig];
                af[mt][2] = As[(r0)     * APAD + kk + tig + 4];
                af[mt][3] = As[(r0 + 8) * APAD + kk + tig + 4];
            }
#pragma unroll
            for (int nt = 0; nt < 8; nt++) {
                int nb = warp_n + nt * 8 + grp;
                unsigned b0 = Bs[(kk + tig)     * BPAD + nb];
                unsigned b1 = Bs[(kk + tig + 4) * BPAD + nb];
#pragma unroll
                for (int mt = 0; mt < 2; mt++)
                    mma_tf32(acc[mt][nt][0], acc[mt][nt][1], acc[mt][nt][2], acc[mt][nt][3],
                             af[mt][0], af[mt][1], af[mt][2], af[mt][3], b0, b1);
            }
        }
        __syncthreads();
    }

    // --- epilogue ---
#pragma unroll
    for (int mt = 0; mt < 2; mt++) {
#pragma unroll
        for (int half = 0; half < 2; half++) {
            int gm = m0 + warp_m + mt * 16 + grp + half * 8;
            if (gm >= M) continue;
#pragma unroll
            for (int nt = 0; nt < 8; nt++) {
                int gn = n0 + warp_n + nt * 8 + tig * 2;
                float v0 = acc[mt][nt][half * 2 + 0];
                float v1 = acc[mt][nt][half * 2 + 1];
                if (EPI >= 1) { v0 += bias[gn]; v1 += bias[gn + 1]; }
                if (EPI == 1) { v0 = fmaxf(v0, 0.0f); v1 = fmaxf(v1, 0.0f); }
                *(float2*)(C + (size_t)gm * N + gn) = make_float2(v0, v1);
            }
        }
    }
}

// ---- per-node attention scores: s = <h[n,h,:], a[h,:]> (one warp per node) ----
__global__ void score_kernel(const float* __restrict__ a_src, const float* __restrict__ a_dst) {
    int gw = (blockIdx.x * blockDim.x + threadIdx.x) >> 5;
    int lane = threadIdx.x & 31;
    if (gw >= NN) return;

    const float4* hp = (const float4*)(g_h + (size_t)gw * HD);
    float4 v0 = hp[lane * 2];
    float4 v1 = hp[lane * 2 + 1];

    int head = lane >> 3;           // 8 lanes cover one head (64 dims)
    int off = (lane & 7) * 8;
    const float4* as = (const float4*)(a_src + head * OUTD + off);
    const float4* ad = (const float4*)(a_dst + head * OUTD + off);
    float4 as0 = as[0], as1 = as[1];
    float4 ad0 = ad[0], ad1 = ad[1];

    float ss = v0.x * as0.x + v0.y * as0.y + v0.z * as0.z + v0.w * as0.w
             + v1.x * as1.x + v1.y * as1.y + v1.z * as1.z + v1.w * as1.w;
    float sd = v0.x * ad0.x + v0.y * ad0.y + v0.z * ad0.z + v0.w * ad0.w
             + v1.x * ad1.x + v1.y * ad1.y + v1.z * ad1.z + v1.w * ad1.w;

#pragma unroll
    for (int o = 4; o > 0; o >>= 1) {
        ss += __shfl_down_sync(0xffffffffu, ss, o);
        sd += __shfl_down_sync(0xffffffffu, sd, o);
    }
    if ((lane & 7) == 0) {
        g_s_src[gw * HEADS + head] = ss;
        g_s_dst[gw * HEADS + head] = sd;
    }
}

__device__ __forceinline__ void red_add_v4(float* p, float x, float y, float z, float w) {
    asm volatile("red.global.add.v4.f32 [%0], {%1, %2, %3, %4};"
                 :: "l"(p), "f"(x), "f"(y), "f"(z), "f"(w) : "memory");
}

// ---- edge kernel: one warp per edge ----
// ex = exp(leaky_relu(s_src[src]+s_dst[dst]))  (segment-max omitted: shift-invariant, fp32-safe)
// den[dst,h] += ex ; num[dst,h,:] += ex * h[src,h,:]
__global__ void edge_kernel(const int* __restrict__ src, const int* __restrict__ dst) {
    int gw = (blockIdx.x * blockDim.x + threadIdx.x) >> 5;
    int lane = threadIdx.x & 31;
    if (gw >= NE) return;

    int s = src[gw];
    int d = dst[gw];

    float ex = 0.0f;
    if (lane < HEADS) {
        float e = g_s_src[s * HEADS + lane] + g_s_dst[d * HEADS + lane];
        e = e > 0.0f ? e : 0.2f * e;
        ex = __expf(e);
        atomicAdd(&g_den[d * HEADS + lane], ex);
    }
    float exh = __shfl_sync(0xffffffffu, ex, lane >> 3);  // head = lane/8

    const float4* hp = (const float4*)(g_h + (size_t)s * HD);
    float4 v0 = hp[lane * 2];
    float4 v1 = hp[lane * 2 + 1];

    float* np = g_num + (size_t)d * HD + lane * 8;
    red_add_v4(np + 0, exh * v0.x, exh * v0.y, exh * v0.z, exh * v0.w);
    red_add_v4(np + 4, exh * v1.x, exh * v1.y, exh * v1.z, exh * v1.w);
}

extern "C" void kernel_launch(void* const* d_in, const int* in_sizes, int n_in,
                              void* d_out, int out_size) {
    const float* node_emb = (const float*)d_in[0];
    const int*   src      = (const int*)d_in[1];
    const int*   dst      = (const int*)d_in[2];
    const float* W_n      = (const float*)d_in[3];
    const float* a_src    = (const float*)d_in[4];
    const float* a_dst    = (const float*)d_in[5];
    const float* W1       = (const float*)d_in[6];
    const float* b1       = (const float*)d_in[7];
    const float* W2       = (const float*)d_in[8];
    const float* b2       = (const float*)d_in[9];
    float* out = (float*)d_out;

    float* h_ptr;      cudaGetSymbolAddress((void**)&h_ptr, g_h);
    float* num_ptr;    cudaGetSymbolAddress((void**)&num_ptr, g_num);
    float* hid_ptr;    cudaGetSymbolAddress((void**)&hid_ptr, g_hidden);
    float* den_ptr;    cudaGetSymbolAddress((void**)&den_ptr, g_den);
    float* wc_ptr;     cudaGetSymbolAddress((void**)&wc_ptr, g_Wc);

    // 1. repack W, zero accumulators
    pack_w_kernel<<<(IND * HD + 255) / 256, 256>>>(W_n);
    zero_kernel<<<(NN * HD + 255) / 256, 256>>>();

    // 2. GEMM1: h = X @ Wc   [50000,128]x[128,256]
    {
        dim3 grid((NN + 127) / 128, HD / 128);
        gemm_tf32_kernel<0, 0><<<grid, 256>>>(node_emb, wc_ptr, nullptr, nullptr,
                                              h_ptr, NN, HD, IND);
    }

    // 3. attention scores per node
    score_kernel<<<(NN * 32 + 255) / 256, 256>>>(a_src, a_dst);

    // 4. edge scatter (softmax numerator/denominator)
    edge_kernel<<<(NE * 32 + 255) / 256, 256>>>(src, dst);

    // 5. GEMM2: hidden = relu( relu(num/den) @ W1 + b1 )   [50000,256]x[256,256]
    {
        dim3 grid((NN + 127) / 128, HID / 128);
        gemm_tf32_kernel<1, 1><<<grid, 256>>>(num_ptr, W1, b1, den_ptr,
                                              hid_ptr, NN, HID, HD);
    }

    // 6. GEMM3: out = hidden @ W2 + b2   [50000,256]x[256,128]
    {
        dim3 grid((NN + 127) / 128, MOUT / 128);
        gemm_tf32_kernel<0, 2><<<grid, 256>>>(hid_ptr, W2, b2, nullptr,
                                              out, NN, MOUT, HID);
    }
}

// round 8
// speedup vs baseline: 1.4449x; 1.4449x over previous
#include <cuda_runtime.h>
#include <cuda_bf16.h>

#define NN 50000
#define NE 800000
#define IND 128
#define OUTD 64
#define HEADS 4
#define HD 256      // HEADS*OUTD
#define HID 256
#define MOUT 128

// ---- scratch (device globals: allocation-free) ----
__device__ float g_h[(size_t)NN * HD];        // per-head transformed features [N, H*D]
__device__ float g_act[(size_t)NN * HD];      // relu(num/den): GEMM2 input
__device__ float g_hidden[(size_t)NN * HID];  // MLP hidden
__device__ float g_s_src[NN * HEADS];
__device__ float g_s_dst[NN * HEADS];
__device__ float g_Wc[IND * HD];              // repacked W_n -> [IND, H*D]
// CSR-by-dst build
__device__ int g_cnt[NN];
__device__ int g_off[NN + 1];
__device__ int g_pos[NN];
__device__ int g_esrc[NE];

// ---- pack W_n [H, IND, OUTD] -> Wc [IND, H*OUTD]; also zero g_cnt ----
__global__ void pack_w_kernel(const float* __restrict__ Wn) {
    int i = blockIdx.x * blockDim.x + threadIdx.x;
    if (i < IND * HD) {
        int c = i / HD;
        int j = i % HD;
        int h = j >> 6;
        int d = j & 63;
        g_Wc[i] = Wn[h * (IND * OUTD) + c * OUTD + d];
    }
    if (i < NN) g_cnt[i] = 0;
}

// ---- histogram of dst ----
__global__ void hist_kernel(const int* __restrict__ dst) {
    int i = blockIdx.x * blockDim.x + threadIdx.x;
    if (i < NE) atomicAdd(&g_cnt[dst[i]], 1);
}

// ---- single-block exclusive scan of g_cnt -> g_off (and copy to g_pos) ----
__global__ void scan_kernel() {
    __shared__ int warp_sums[32];
    __shared__ int s_carry;
    int tid = threadIdx.x;           // 1024 threads
    int lane = tid & 31;
    int wid = tid >> 5;
    if (tid == 0) s_carry = 0;
    __syncthreads();

    for (int base = 0; base < NN; base += 1024) {
        int i = base + tid;
        int v = (i < NN) ? g_cnt[i] : 0;
        int x = v;
#pragma unroll
        for (int o = 1; o < 32; o <<= 1) {
            int t = __shfl_up_sync(0xffffffffu, x, o);
            if (lane >= o) x += t;
        }
        if (lane == 31) warp_sums[wid] = x;
        __syncthreads();
        if (wid == 0) {
            int s = warp_sums[lane];
#pragma unroll
            for (int o = 1; o < 32; o <<= 1) {
                int t = __shfl_up_sync(0xffffffffu, s, o);
                if (lane >= o) s += t;
            }
            warp_sums[lane] = s;
        }
        __syncthreads();
        int warp_off = (wid > 0) ? warp_sums[wid - 1] : 0;
        int incl = x + warp_off + s_carry;
        int excl = incl - v;
        if (i < NN) { g_off[i] = excl; g_pos[i] = excl; }
        __syncthreads();                 // all reads of s_carry done
        if (tid == 1023) s_carry = incl;
        __syncthreads();
    }
    if (tid == 0) g_off[NN] = s_carry;   // == NE
}

// ---- scatter edges into dst-grouped order ----
__global__ void scatter_kernel(const int* __restrict__ src, const int* __restrict__ dst) {
    int i = blockIdx.x * blockDim.x + threadIdx.x;
    if (i < NE) {
        int d = dst[i];
        int p = atomicAdd(&g_pos[d], 1);
        g_esrc[p] = src[i];
    }
}

__device__ __forceinline__ unsigned f2tf32(float f) {
    unsigned r;
    asm("cvt.rna.tf32.f32 %0, %1;" : "=r"(r) : "f"(f));
    return r;
}

__device__ __forceinline__ void mma_tf32(float& c0, float& c1, float& c2, float& c3,
                                         unsigned a0, unsigned a1, unsigned a2, unsigned a3,
                                         unsigned b0, unsigned b1) {
    asm volatile("mma.sync.aligned.m16n8k8.row.col.f32.tf32.tf32.f32 "
                 "{%0,%1,%2,%3}, {%4,%5,%6,%7}, {%8,%9}, {%0,%1,%2,%3};"
                 : "+f"(c0), "+f"(c1), "+f"(c2), "+f"(c3)
                 : "r"(a0), "r"(a1), "r"(a2), "r"(a3), "r"(b0), "r"(b1));
}

// ---- tf32 tensor-core GEMM: C[M,N] = act(A @ B + bias) ----
// EPI 0: none. 1: +bias, relu. 2: +bias.
template<int EPI>
__global__ void __launch_bounds__(256)
gemm_tf32_kernel(const float* __restrict__ A, const float* __restrict__ B,
                 const float* __restrict__ bias,
                 float* __restrict__ C, int M, int N, int K)
{
    const int BM = 128, BN = 128, BK = 32;
    const int APAD = 36;
    const int BPAD = 136;
    __shared__ unsigned As[BM * APAD];   // [m][k]
    __shared__ unsigned Bs[BK * BPAD];   // [k][n]

    int tid = threadIdx.x;
    int wid = tid >> 5;
    int lane = tid & 31;
    int grp = lane >> 2;
    int tig = lane & 3;

    int warp_m = (wid & 3) * 32;
    int warp_n = (wid >> 2) * 64;

    int m0 = blockIdx.x * BM;
    int n0 = blockIdx.y * BN;

    float acc[2][8][4];
#pragma unroll
    for (int i = 0; i < 2; i++)
#pragma unroll
        for (int j = 0; j < 8; j++)
#pragma unroll
            for (int q = 0; q < 4; q++) acc[i][j][q] = 0.0f;

    for (int k0 = 0; k0 < K; k0 += BK) {
#pragma unroll
        for (int j = 0; j < 4; j++) {
            int i = tid + j * 256;
            int row = i >> 3;
            int c4 = (i & 7) * 4;
            int gm = m0 + row;
            float4 v = make_float4(0.f, 0.f, 0.f, 0.f);
            if (gm < M) v = *(const float4*)(A + (size_t)gm * K + k0 + c4);
            unsigned* p = &As[row * APAD + c4];
            p[0] = f2tf32(v.x); p[1] = f2tf32(v.y);
            p[2] = f2tf32(v.z); p[3] = f2tf32(v.w);
        }
#pragma unroll
        for (int j = 0; j < 4; j++) {
            int i = tid + j * 256;
            int row = i >> 5;
            int c4 = (i & 31) * 4;
            float4 v = *(const float4*)(B + (size_t)(k0 + row) * N + n0 + c4);
            unsigned* p = &Bs[row * BPAD + c4];
            p[0] = f2tf32(v.x); p[1] = f2tf32(v.y);
            p[2] = f2tf32(v.z); p[3] = f2tf32(v.w);
        }
        __syncthreads();

#pragma unroll
        for (int kk = 0; kk < BK; kk += 8) {
            unsigned af[2][4];
#pragma unroll
            for (int mt = 0; mt < 2; mt++) {
                int r0 = warp_m + mt * 16 + grp;
                af[mt][0] = As[(r0)     * APAD + kk + tig];
                af[mt][1] = As[(r0 + 8) * APAD + kk + tig];
                af[mt][2] = As[(r0)     * APAD + kk + tig + 4];
                af[mt][3] = As[(r0 + 8) * APAD + kk + tig + 4];
            }
#pragma unroll
            for (int nt = 0; nt < 8; nt++) {
                int nb = warp_n + nt * 8 + grp;
                unsigned b0 = Bs[(kk + tig)     * BPAD + nb];
                unsigned b1 = Bs[(kk + tig + 4) * BPAD + nb];
#pragma unroll
                for (int mt = 0; mt < 2; mt++)
                    mma_tf32(acc[mt][nt][0], acc[mt][nt][1], acc[mt][nt][2], acc[mt][nt][3],
                             af[mt][0], af[mt][1], af[mt][2], af[mt][3], b0, b1);
            }
        }
        __syncthreads();
    }

#pragma unroll
    for (int mt = 0; mt < 2; mt++) {
#pragma unroll
        for (int half = 0; half < 2; half++) {
            int gm = m0 + warp_m + mt * 16 + grp + half * 8;
            if (gm >= M) continue;
#pragma unroll
            for (int nt = 0; nt < 8; nt++) {
                int gn = n0 + warp_n + nt * 8 + tig * 2;
                float v0 = acc[mt][nt][half * 2 + 0];
                float v1 = acc[mt][nt][half * 2 + 1];
                if (EPI >= 1) { v0 += bias[gn]; v1 += bias[gn + 1]; }
                if (EPI == 1) { v0 = fmaxf(v0, 0.0f); v1 = fmaxf(v1, 0.0f); }
                *(float2*)(C + (size_t)gm * N + gn) = make_float2(v0, v1);
            }
        }
    }
}

// ---- per-node attention scores: s = <h[n,h,:], a[h,:]> (one warp per node) ----
__global__ void score_kernel(const float* __restrict__ a_src, const float* __restrict__ a_dst) {
    int gw = (blockIdx.x * blockDim.x + threadIdx.x) >> 5;
    int lane = threadIdx.x & 31;
    if (gw >= NN) return;

    const float4* hp = (const float4*)(g_h + (size_t)gw * HD);
    float4 v0 = hp[lane * 2];
    float4 v1 = hp[lane * 2 + 1];

    int head = lane >> 3;
    int off = (lane & 7) * 8;
    const float4* as = (const float4*)(a_src + head * OUTD + off);
    const float4* ad = (const float4*)(a_dst + head * OUTD + off);
    float4 as0 = as[0], as1 = as[1];
    float4 ad0 = ad[0], ad1 = ad[1];

    float ss = v0.x * as0.x + v0.y * as0.y + v0.z * as0.z + v0.w * as0.w
             + v1.x * as1.x + v1.y * as1.y + v1.z * as1.z + v1.w * as1.w;
    float sd = v0.x * ad0.x + v0.y * ad0.y + v0.z * ad0.z + v0.w * ad0.w
             + v1.x * ad1.x + v1.y * ad1.y + v1.z * ad1.z + v1.w * ad1.w;

#pragma unroll
    for (int o = 4; o > 0; o >>= 1) {
        ss += __shfl_down_sync(0xffffffffu, ss, o);
        sd += __shfl_down_sync(0xffffffffu, sd, o);
    }
    if ((lane & 7) == 0) {
        g_s_src[gw * HEADS + head] = ss;
        g_s_dst[gw * HEADS + head] = sd;
    }
}

// ---- gather kernel: one warp per dst node, CSR edges, register accumulation ----
// g_act[n] = relu( (Σ_e ex_e * h[src_e]) / (Σ_e ex_e) ), ex = exp(lrelu(s_src+s_dst))
__global__ void gather_kernel() {
    int gw = (blockIdx.x * blockDim.x + threadIdx.x) >> 5;
    int lane = threadIdx.x & 31;
    if (gw >= NN) return;

    int beg = g_off[gw];
    int end = g_off[gw + 1];
    int head = lane >> 3;

    float sdst = (lane < HEADS) ? g_s_dst[gw * HEADS + lane] : 0.0f;

    float4 a0 = make_float4(0.f, 0.f, 0.f, 0.f);
    float4 a1 = make_float4(0.f, 0.f, 0.f, 0.f);
    float den = 0.0f;

    for (int chunk = beg; chunk < end; chunk += 32) {
        int myE = (chunk + lane < end) ? g_esrc[chunk + lane] : 0;
        int cnt = min(32, end - chunk);
        for (int j = 0; j < cnt; j++) {
            int s = __shfl_sync(0xffffffffu, myE, j);
            float ex = 0.0f;
            if (lane < HEADS) {
                float e = g_s_src[s * HEADS + lane] + sdst;
                e = e > 0.0f ? e : 0.2f * e;
                ex = __expf(e);
                den += ex;
            }
            float exh = __shfl_sync(0xffffffffu, ex, head);
            const float4* hp = (const float4*)(g_h + (size_t)s * HD);
            float4 v0 = hp[lane * 2];
            float4 v1 = hp[lane * 2 + 1];
            a0.x = fmaf(exh, v0.x, a0.x); a0.y = fmaf(exh, v0.y, a0.y);
            a0.z = fmaf(exh, v0.z, a0.z); a0.w = fmaf(exh, v0.w, a0.w);
            a1.x = fmaf(exh, v1.x, a1.x); a1.y = fmaf(exh, v1.y, a1.y);
            a1.z = fmaf(exh, v1.z, a1.z); a1.w = fmaf(exh, v1.w, a1.w);
        }
    }

    float denh = __shfl_sync(0xffffffffu, den, head);
    float inv = denh > 0.0f ? 1.0f / denh : 0.0f;
    a0.x = fmaxf(a0.x * inv, 0.0f); a0.y = fmaxf(a0.y * inv, 0.0f);
    a0.z = fmaxf(a0.z * inv, 0.0f); a0.w = fmaxf(a0.w * inv, 0.0f);
    a1.x = fmaxf(a1.x * inv, 0.0f); a1.y = fmaxf(a1.y * inv, 0.0f);
    a1.z = fmaxf(a1.z * inv, 0.0f); a1.w = fmaxf(a1.w * inv, 0.0f);

    float4* op = (float4*)(g_act + (size_t)gw * HD);
    op[lane * 2]     = a0;
    op[lane * 2 + 1] = a1;
}

extern "C" void kernel_launch(void* const* d_in, const int* in_sizes, int n_in,
                              void* d_out, int out_size) {
    const float* node_emb = (const float*)d_in[0];
    const int*   src      = (const int*)d_in[1];
    const int*   dst      = (const int*)d_in[2];
    const float* W_n      = (const float*)d_in[3];
    const float* a_src    = (const float*)d_in[4];
    const float* a_dst    = (const float*)d_in[5];
    const float* W1       = (const float*)d_in[6];
    const float* b1       = (const float*)d_in[7];
    const float* W2       = (const float*)d_in[8];
    const float* b2       = (const float*)d_in[9];
    float* out = (float*)d_out;

    float* h_ptr;   cudaGetSymbolAddress((void**)&h_ptr, g_h);
    float* act_ptr; cudaGetSymbolAddress((void**)&act_ptr, g_act);
    float* hid_ptr; cudaGetSymbolAddress((void**)&hid_ptr, g_hidden);
    float* wc_ptr;  cudaGetSymbolAddress((void**)&wc_ptr, g_Wc);

    // 1. pack W + zero counts
    pack_w_kernel<<<(NN + 255) / 256, 256>>>(W_n);

    // 2. CSR-by-dst build
    hist_kernel<<<(NE + 255) / 256, 256>>>(dst);
    scan_kernel<<<1, 1024>>>();
    scatter_kernel<<<(NE + 255) / 256, 256>>>(src, dst);

    // 3. GEMM1: h = X @ Wc   [50000,128]x[128,256]
    {
        dim3 grid((NN + 127) / 128, HD / 128);
        gemm_tf32_kernel<0><<<grid, 256>>>(node_emb, wc_ptr, nullptr, h_ptr, NN, HD, IND);
    }

    // 4. attention scores per node
    score_kernel<<<(NN * 32 + 255) / 256, 256>>>(a_src, a_dst);

    // 5. gather: per-dst softmax-weighted aggregation -> g_act (normalized + relu)
    gather_kernel<<<(NN * 32 + 255) / 256, 256>>>();

    // 6. GEMM2: hidden = relu( g_act @ W1 + b1 )   [50000,256]x[256,256]
    {
        dim3 grid((NN + 127) / 128, HID / 128);
        gemm_tf32_kernel<1><<<grid, 256>>>(act_ptr, W1, b1, hid_ptr, NN, HID, HD);
    }

    // 7. GEMM3: out = hidden @ W2 + b2   [50000,256]x[256,128]
    {
        dim3 grid((NN + 127) / 128, MOUT / 128);
        gemm_tf32_kernel<2><<<grid, 256>>>(hid_ptr, W2, b2, out, NN, MOUT, HID);
    }
}

// round 9
// speedup vs baseline: 1.8927x; 1.3099x over previous
#include <cuda_runtime.h>
#include <cuda_bf16.h>

#define NN 50000
#define NE 800000
#define IND 128
#define OUTD 64
#define HEADS 4
#define HD 256      // HEADS*OUTD
#define HID 256
#define MOUT 128
#define NBLK 49     // ceil(NN/1024)

// ---- scratch (device globals: allocation-free) ----
__device__ float g_h[(size_t)NN * HD];        // per-head transformed features [N, H*D]
__device__ float g_act[(size_t)NN * HD];      // relu(num/den): GEMM2 input
__device__ float g_hidden[(size_t)NN * HID];  // MLP hidden
__device__ float g_s_src[NN * HEADS];
__device__ float g_s_dst[NN * HEADS];
__device__ float g_Wc[IND * HD];              // repacked W_n -> [IND, H*D]
// CSR-by-dst build
__device__ int g_cnt[NN];
__device__ int g_off[NN + 1];
__device__ int g_pos[NN];
__device__ int g_esrc[NE];
__device__ int g_bsum[NBLK];
__device__ int g_boff[NBLK];

// ---- pack W_n [H, IND, OUTD] -> Wc [IND, H*OUTD]; also zero g_cnt ----
__global__ void pack_w_kernel(const float* __restrict__ Wn) {
    int i = blockIdx.x * blockDim.x + threadIdx.x;
    if (i < IND * HD) {
        int c = i / HD;
        int j = i % HD;
        int h = j >> 6;
        int d = j & 63;
        g_Wc[i] = Wn[h * (IND * OUTD) + c * OUTD + d];
    }
    if (i < NN) g_cnt[i] = 0;
}

// ---- histogram of dst ----
__global__ void hist_kernel(const int* __restrict__ dst) {
    int i = blockIdx.x * blockDim.x + threadIdx.x;
    if (i < NE) atomicAdd(&g_cnt[dst[i]], 1);
}

// ---- 3-phase scan: block sums -> top scan -> per-block scan ----
__global__ void scan_blocks_kernel() {
    __shared__ int wsum[32];
    int tid = threadIdx.x;                 // 1024
    int i = blockIdx.x * 1024 + tid;
    int v = (i < NN) ? g_cnt[i] : 0;
#pragma unroll
    for (int o = 16; o > 0; o >>= 1) v += __shfl_down_sync(0xffffffffu, v, o);
    if ((tid & 31) == 0) wsum[tid >> 5] = v;
    __syncthreads();
    if (tid < 32) {
        int s = wsum[tid];
#pragma unroll
        for (int o = 16; o > 0; o >>= 1) s += __shfl_down_sync(0xffffffffu, s, o);
        if (tid == 0) g_bsum[blockIdx.x] = s;
    }
}

__global__ void scan_top_kernel() {
    __shared__ int s[64];
    int t = threadIdx.x;                   // 64
    int v = (t < NBLK) ? g_bsum[t] : 0;
    s[t] = v;
    __syncthreads();
#pragma unroll
    for (int o = 1; o < 64; o <<= 1) {
        int x = (t >= o) ? s[t - o] : 0;
        __syncthreads();
        s[t] += x;
        __syncthreads();
    }
    if (t < NBLK) g_boff[t] = s[t] - v;
    if (t == 0) g_off[NN] = NE;
}

__global__ void scan_final_kernel() {
    __shared__ int wsum[32];
    int tid = threadIdx.x;                 // 1024
    int lane = tid & 31;
    int wid = tid >> 5;
    int i = blockIdx.x * 1024 + tid;
    int v = (i < NN) ? g_cnt[i] : 0;
    int x = v;
#pragma unroll
    for (int o = 1; o < 32; o <<= 1) {
        int t = __shfl_up_sync(0xffffffffu, x, o);
        if (lane >= o) x += t;
    }
    if (lane == 31) wsum[wid] = x;
    __syncthreads();
    if (wid == 0) {
        int s = wsum[lane];
#pragma unroll
        for (int o = 1; o < 32; o <<= 1) {
            int t = __shfl_up_sync(0xffffffffu, s, o);
            if (lane >= o) s += t;
        }
        wsum[lane] = s;
    }
    __syncthreads();
    int excl = x - v + ((wid > 0) ? wsum[wid - 1] : 0) + g_boff[blockIdx.x];
    if (i < NN) { g_off[i] = excl; g_pos[i] = excl; }
}

// ---- scatter edges into dst-grouped order ----
__global__ void scatter_kernel(const int* __restrict__ src, const int* __restrict__ dst) {
    int i = blockIdx.x * blockDim.x + threadIdx.x;
    if (i < NE) {
        int d = dst[i];
        int p = atomicAdd(&g_pos[d], 1);
        g_esrc[p] = src[i];
    }
}

__device__ __forceinline__ unsigned f2tf32(float f) {
    unsigned r;
    asm("cvt.rna.tf32.f32 %0, %1;" : "=r"(r) : "f"(f));
    return r;
}

__device__ __forceinline__ void mma_tf32(float& c0, float& c1, float& c2, float& c3,
                                         unsigned a0, unsigned a1, unsigned a2, unsigned a3,
                                         unsigned b0, unsigned b1) {
    asm volatile("mma.sync.aligned.m16n8k8.row.col.f32.tf32.tf32.f32 "
                 "{%0,%1,%2,%3}, {%4,%5,%6,%7}, {%8,%9}, {%0,%1,%2,%3};"
                 : "+f"(c0), "+f"(c1), "+f"(c2), "+f"(c3)
                 : "r"(a0), "r"(a1), "r"(a2), "r"(a3), "r"(b0), "r"(b1));
}

// ---- tf32 tensor-core GEMM with register prefetch ----
// C[M,N] = act(A @ B + bias). EPI 0: none. 1: +bias, relu. 2: +bias.
// SCORE 1: also emit g_s_src/g_s_dst = <C_row(head), a_src/a_dst> (GEMM1 only).
template<int EPI, int SCORE>
__global__ void __launch_bounds__(256, 2)
gemm_tf32_kernel(const float* __restrict__ A, const float* __restrict__ B,
                 const float* __restrict__ bias,
                 const float* __restrict__ asrc, const float* __restrict__ adst,
                 float* __restrict__ C, int M, int N, int K)
{
    const int BM = 128, BN = 128, BK = 32;
    const int APAD = 36;
    const int BPAD = 136;
    __shared__ unsigned As[BM * APAD];   // [m][k]
    __shared__ unsigned Bs[BK * BPAD];   // [k][n]

    int tid = threadIdx.x;
    int wid = tid >> 5;
    int lane = tid & 31;
    int grp = lane >> 2;
    int tig = lane & 3;

    int warp_m = (wid & 3) * 32;
    int warp_n = (wid >> 2) * 64;

    int m0 = blockIdx.x * BM;
    int n0 = blockIdx.y * BN;

    // per-thread load coords
    int a_row = tid >> 1;                // 0..127 (2 float4 per row per k-tile)
    int a_c4 = (tid & 1) * 4;            // covers 8 of 32 cols; x4 j-loop covers rest? no:
    // A tile is 128 rows x 32 cols = 1024 float4; 256 threads x 4.
    // mapping: i = tid + j*256 ; row = i>>3 ; c4 = (i&7)*4
    int b_rowbase;
    (void)a_row; (void)a_c4; (void)b_rowbase;

    float4 ra[4], rb[4];

    // prologue loads (k0 = 0)
#pragma unroll
    for (int j = 0; j < 4; j++) {
        int i = tid + j * 256;
        int row = i >> 3;
        int c4 = (i & 7) * 4;
        int gm = m0 + row;
        ra[j] = make_float4(0.f, 0.f, 0.f, 0.f);
        if (gm < M) ra[j] = *(const float4*)(A + (size_t)gm * K + c4);
    }
#pragma unroll
    for (int j = 0; j < 4; j++) {
        int i = tid + j * 256;
        int row = i >> 5;
        int c4 = (i & 31) * 4;
        rb[j] = *(const float4*)(B + (size_t)row * N + n0 + c4);
    }

    float acc[2][8][4];
#pragma unroll
    for (int i = 0; i < 2; i++)
#pragma unroll
        for (int j = 0; j < 8; j++)
#pragma unroll
            for (int q = 0; q < 4; q++) acc[i][j][q] = 0.0f;

    for (int k0 = 0; k0 < K; k0 += BK) {
        // store current tile (registers -> smem, tf32 convert)
#pragma unroll
        for (int j = 0; j < 4; j++) {
            int i = tid + j * 256;
            int row = i >> 3;
            int c4 = (i & 7) * 4;
            unsigned* p = &As[row * APAD + c4];
            p[0] = f2tf32(ra[j].x); p[1] = f2tf32(ra[j].y);
            p[2] = f2tf32(ra[j].z); p[3] = f2tf32(ra[j].w);
        }
#pragma unroll
        for (int j = 0; j < 4; j++) {
            int i = tid + j * 256;
            int row = i >> 5;
            int c4 = (i & 31) * 4;
            unsigned* p = &Bs[row * BPAD + c4];
            p[0] = f2tf32(rb[j].x); p[1] = f2tf32(rb[j].y);
            p[2] = f2tf32(rb[j].z); p[3] = f2tf32(rb[j].w);
        }
        __syncthreads();

        // prefetch next tile while computing
        int kn = k0 + BK;
        if (kn < K) {
#pragma unroll
            for (int j = 0; j < 4; j++) {
                int i = tid + j * 256;
                int row = i >> 3;
                int c4 = (i & 7) * 4;
                int gm = m0 + row;
                ra[j] = make_float4(0.f, 0.f, 0.f, 0.f);
                if (gm < M) ra[j] = *(const float4*)(A + (size_t)gm * K + kn + c4);
            }
#pragma unroll
            for (int j = 0; j < 4; j++) {
                int i = tid + j * 256;
                int row = i >> 5;
                int c4 = (i & 31) * 4;
                rb[j] = *(const float4*)(B + (size_t)(kn + row) * N + n0 + c4);
            }
        }

#pragma unroll
        for (int kk = 0; kk < BK; kk += 8) {
            unsigned af[2][4];
#pragma unroll
            for (int mt = 0; mt < 2; mt++) {
                int r0 = warp_m + mt * 16 + grp;
                af[mt][0] = As[(r0)     * APAD + kk + tig];
                af[mt][1] = As[(r0 + 8) * APAD + kk + tig];
                af[mt][2] = As[(r0)     * APAD + kk + tig + 4];
                af[mt][3] = As[(r0 + 8) * APAD + kk + tig + 4];
            }
#pragma unroll
            for (int nt = 0; nt < 8; nt++) {
                int nb = warp_n + nt * 8 + grp;
                unsigned b0 = Bs[(kk + tig)     * BPAD + nb];
                unsigned b1 = Bs[(kk + tig + 4) * BPAD + nb];
#pragma unroll
                for (int mt = 0; mt < 2; mt++)
                    mma_tf32(acc[mt][nt][0], acc[mt][nt][1], acc[mt][nt][2], acc[mt][nt][3],
                             af[mt][0], af[mt][1], af[mt][2], af[mt][3], b0, b1);
            }
        }
        __syncthreads();
    }

    // --- epilogue: C store (+ optional fused attention scores) ---
    int head = (n0 + warp_n) >> 6;   // warp tile spans exactly one head (64 cols)
#pragma unroll
    for (int mt = 0; mt < 2; mt++) {
#pragma unroll
        for (int half = 0; half < 2; half++) {
            int gm = m0 + warp_m + mt * 16 + grp + half * 8;
            if (gm >= M) continue;
            float ss = 0.0f, sd = 0.0f;
#pragma unroll
            for (int nt = 0; nt < 8; nt++) {
                int gn = n0 + warp_n + nt * 8 + tig * 2;
                float v0 = acc[mt][nt][half * 2 + 0];
                float v1 = acc[mt][nt][half * 2 + 1];
                if (EPI >= 1) { v0 += bias[gn]; v1 += bias[gn + 1]; }
                if (EPI == 1) { v0 = fmaxf(v0, 0.0f); v1 = fmaxf(v1, 0.0f); }
                if (SCORE) {
                    float2 a2 = *(const float2*)(asrc + gn);
                    float2 d2 = *(const float2*)(adst + gn);
                    ss += v0 * a2.x + v1 * a2.y;
                    sd += v0 * d2.x + v1 * d2.y;
                }
                *(float2*)(C + (size_t)gm * N + gn) = make_float2(v0, v1);
            }
            if (SCORE) {
                ss += __shfl_down_sync(0xffffffffu, ss, 2);
                ss += __shfl_down_sync(0xffffffffu, ss, 1);
                sd += __shfl_down_sync(0xffffffffu, sd, 2);
                sd += __shfl_down_sync(0xffffffffu, sd, 1);
                if (tig == 0) {
                    g_s_src[gm * HEADS + head] = ss;
                    g_s_dst[gm * HEADS + head] = sd;
                }
            }
        }
    }
}

// ---- gather kernel: one warp per dst node, CSR edges, register accumulation ----
__global__ void gather_kernel() {
    int gw = (blockIdx.x * blockDim.x + threadIdx.x) >> 5;
    int lane = threadIdx.x & 31;
    if (gw >= NN) return;

    int beg = g_off[gw];
    int end = g_off[gw + 1];
    int head = lane >> 3;

    float sdst = (lane < HEADS) ? g_s_dst[gw * HEADS + lane] : 0.0f;

    float4 a0 = make_float4(0.f, 0.f, 0.f, 0.f);
    float4 a1 = make_float4(0.f, 0.f, 0.f, 0.f);
    float den = 0.0f;

    for (int chunk = beg; chunk < end; chunk += 32) {
        int myE = (chunk + lane < end) ? g_esrc[chunk + lane] : 0;
        int cnt = min(32, end - chunk);
        for (int j = 0; j < cnt; j++) {
            int s = __shfl_sync(0xffffffffu, myE, j);
            float ex = 0.0f;
            if (lane < HEADS) {
                float e = g_s_src[s * HEADS + lane] + sdst;
                e = e > 0.0f ? e : 0.2f * e;
                ex = __expf(e);
                den += ex;
            }
            float exh = __shfl_sync(0xffffffffu, ex, head);
            const float4* hp = (const float4*)(g_h + (size_t)s * HD);
            float4 v0 = hp[lane * 2];
            float4 v1 = hp[lane * 2 + 1];
            a0.x = fmaf(exh, v0.x, a0.x); a0.y = fmaf(exh, v0.y, a0.y);
            a0.z = fmaf(exh, v0.z, a0.z); a0.w = fmaf(exh, v0.w, a0.w);
            a1.x = fmaf(exh, v1.x, a1.x); a1.y = fmaf(exh, v1.y, a1.y);
            a1.z = fmaf(exh, v1.z, a1.z); a1.w = fmaf(exh, v1.w, a1.w);
        }
    }

    float denh = __shfl_sync(0xffffffffu, den, head);
    float inv = denh > 0.0f ? 1.0f / denh : 0.0f;
    a0.x = fmaxf(a0.x * inv, 0.0f); a0.y = fmaxf(a0.y * inv, 0.0f);
    a0.z = fmaxf(a0.z * inv, 0.0f); a0.w = fmaxf(a0.w * inv, 0.0f);
    a1.x = fmaxf(a1.x * inv, 0.0f); a1.y = fmaxf(a1.y * inv, 0.0f);
    a1.z = fmaxf(a1.z * inv, 0.0f); a1.w = fmaxf(a1.w * inv, 0.0f);

    float4* op = (float4*)(g_act + (size_t)gw * HD);
    op[lane * 2]     = a0;
    op[lane * 2 + 1] = a1;
}

extern "C" void kernel_launch(void* const* d_in, const int* in_sizes, int n_in,
                              void* d_out, int out_size) {
    const float* node_emb = (const float*)d_in[0];
    const int*   src      = (const int*)d_in[1];
    const int*   dst      = (const int*)d_in[2];
    const float* W_n      = (const float*)d_in[3];
    const float* a_src    = (const float*)d_in[4];
    const float* a_dst    = (const float*)d_in[5];
    const float* W1       = (const float*)d_in[6];
    const float* b1       = (const float*)d_in[7];
    const float* W2       = (const float*)d_in[8];
    const float* b2       = (const float*)d_in[9];
    float* out = (float*)d_out;

    float* h_ptr;   cudaGetSymbolAddress((void**)&h_ptr, g_h);
    float* act_ptr; cudaGetSymbolAddress((void**)&act_ptr, g_act);
    float* hid_ptr; cudaGetSymbolAddress((void**)&hid_ptr, g_hidden);
    float* wc_ptr;  cudaGetSymbolAddress((void**)&wc_ptr, g_Wc);

    // 1. pack W + zero counts
    pack_w_kernel<<<(NN + 255) / 256, 256>>>(W_n);

    // 2. CSR-by-dst build
    hist_kernel<<<(NE + 255) / 256, 256>>>(dst);
    scan_blocks_kernel<<<NBLK, 1024>>>();
    scan_top_kernel<<<1, 64>>>();
    scan_final_kernel<<<NBLK, 1024>>>();
    scatter_kernel<<<(NE + 255) / 256, 256>>>(src, dst);

    // 3. GEMM1 + fused scores: h = X @ Wc ; s_src/s_dst
    {
        dim3 grid((NN + 127) / 128, HD / 128);
        gemm_tf32_kernel<0, 1><<<grid, 256>>>(node_emb, wc_ptr, nullptr,
                                              a_src, a_dst, h_ptr, NN, HD, IND);
    }

    // 4. gather: per-dst softmax-weighted aggregation -> g_act (normalized + relu)
    gather_kernel<<<(NN * 32 + 255) / 256, 256>>>();

    // 5. GEMM2: hidden = relu( g_act @ W1 + b1 )
    {
        dim3 grid((NN + 127) / 128, HID / 128);
        gemm_tf32_kernel<1, 0><<<grid, 256>>>(act_ptr, W1, b1,
                                              nullptr, nullptr, hid_ptr, NN, HID, HD);
    }

    // 6. GEMM3: out = hidden @ W2 + b2
    {
        dim3 grid((NN + 127) / 128, MOUT / 128);
        gemm_tf32_kernel<2, 0><<<grid, 256>>>(hid_ptr, W2, b2,
                                              nullptr, nullptr, out, NN, MOUT, HID);
    }
}

// round 10
// speedup vs baseline: 2.2092x; 1.1673x over previous
#include <cuda_runtime.h>
#include <cuda_fp16.h>
#include <cuda_bf16.h>

#define NN 50000
#define NE 800000
#define IND 128
#define OUTD 64
#define HEADS 4
#define HD 256      // HEADS*OUTD
#define HID 256
#define MOUT 128
#define NBLK 49     // ceil(NN/1024)

// ---- scratch (device globals: allocation-free) ----
__device__ __half g_h[(size_t)NN * HD];       // transformed features (fp16, gather-only)
__device__ __half g_act[(size_t)NN * HD];     // relu(num/den): GEMM2 input (fp16)
__device__ __half g_hidden[(size_t)NN * HID]; // MLP hidden (fp16)
__device__ float g_s_src[NN * HEADS];
__device__ float g_s_dst[NN * HEADS];
__device__ float g_Wc[IND * HD];              // repacked W_n -> [IND, H*D]
// CSR-by-dst build
__device__ int g_cnt[NN];
__device__ int g_off[NN + 1];
__device__ int g_pos[NN];
__device__ int g_esrc[NE];
__device__ int g_bsum[NBLK];
__device__ int g_boff[NBLK];

// ---- pack W_n [H, IND, OUTD] -> Wc [IND, H*OUTD]; also zero g_cnt ----
__global__ void pack_w_kernel(const float* __restrict__ Wn) {
    int i = blockIdx.x * blockDim.x + threadIdx.x;
    if (i < IND * HD) {
        int c = i / HD;
        int j = i % HD;
        int h = j >> 6;
        int d = j & 63;
        g_Wc[i] = Wn[h * (IND * OUTD) + c * OUTD + d];
    }
    if (i < NN) g_cnt[i] = 0;
}

// ---- histogram of dst ----
__global__ void hist_kernel(const int* __restrict__ dst) {
    int i = blockIdx.x * blockDim.x + threadIdx.x;
    if (i < NE) atomicAdd(&g_cnt[dst[i]], 1);
}

// ---- 3-phase scan ----
__global__ void scan_blocks_kernel() {
    __shared__ int wsum[32];
    int tid = threadIdx.x;
    int i = blockIdx.x * 1024 + tid;
    int v = (i < NN) ? g_cnt[i] : 0;
#pragma unroll
    for (int o = 16; o > 0; o >>= 1) v += __shfl_down_sync(0xffffffffu, v, o);
    if ((tid & 31) == 0) wsum[tid >> 5] = v;
    __syncthreads();
    if (tid < 32) {
        int s = wsum[tid];
#pragma unroll
        for (int o = 16; o > 0; o >>= 1) s += __shfl_down_sync(0xffffffffu, s, o);
        if (tid == 0) g_bsum[blockIdx.x] = s;
    }
}

__global__ void scan_top_kernel() {
    __shared__ int s[64];
    int t = threadIdx.x;
    int v = (t < NBLK) ? g_bsum[t] : 0;
    s[t] = v;
    __syncthreads();
#pragma unroll
    for (int o = 1; o < 64; o <<= 1) {
        int x = (t >= o) ? s[t - o] : 0;
        __syncthreads();
        s[t] += x;
        __syncthreads();
    }
    if (t < NBLK) g_boff[t] = s[t] - v;
    if (t == 0) g_off[NN] = NE;
}

__global__ void scan_final_kernel() {
    __shared__ int wsum[32];
    int tid = threadIdx.x;
    int lane = tid & 31;
    int wid = tid >> 5;
    int i = blockIdx.x * 1024 + tid;
    int v = (i < NN) ? g_cnt[i] : 0;
    int x = v;
#pragma unroll
    for (int o = 1; o < 32; o <<= 1) {
        int t = __shfl_up_sync(0xffffffffu, x, o);
        if (lane >= o) x += t;
    }
    if (lane == 31) wsum[wid] = x;
    __syncthreads();
    if (wid == 0) {
        int s = wsum[lane];
#pragma unroll
        for (int o = 1; o < 32; o <<= 1) {
            int t = __shfl_up_sync(0xffffffffu, s, o);
            if (lane >= o) s += t;
        }
        wsum[lane] = s;
    }
    __syncthreads();
    int excl = x - v + ((wid > 0) ? wsum[wid - 1] : 0) + g_boff[blockIdx.x];
    if (i < NN) { g_off[i] = excl; g_pos[i] = excl; }
}

// ---- scatter edges into dst-grouped order ----
__global__ void scatter_kernel(const int* __restrict__ src, const int* __restrict__ dst) {
    int i = blockIdx.x * blockDim.x + threadIdx.x;
    if (i < NE) {
        int d = dst[i];
        int p = atomicAdd(&g_pos[d], 1);
        g_esrc[p] = src[i];
    }
}

__device__ __forceinline__ unsigned f2tf32(float f) {
    unsigned r;
    asm("cvt.rna.tf32.f32 %0, %1;" : "=r"(r) : "f"(f));
    return r;
}

__device__ __forceinline__ void mma_tf32(float& c0, float& c1, float& c2, float& c3,
                                         unsigned a0, unsigned a1, unsigned a2, unsigned a3,
                                         unsigned b0, unsigned b1) {
    asm volatile("mma.sync.aligned.m16n8k8.row.col.f32.tf32.tf32.f32 "
                 "{%0,%1,%2,%3}, {%4,%5,%6,%7}, {%8,%9}, {%0,%1,%2,%3};"
                 : "+f"(c0), "+f"(c1), "+f"(c2), "+f"(c3)
                 : "r"(a0), "r"(a1), "r"(a2), "r"(a3), "r"(b0), "r"(b1));
}

// ---- tf32 tensor-core GEMM with register prefetch ----
// EPI 0: none. 1: +bias, relu. 2: +bias.
// SCORE 1: emit g_s_src/g_s_dst from fp32 accumulators (GEMM1 only).
// AHALF: A matrix is fp16. CHALF: C output is fp16.
template<int EPI, int SCORE, int AHALF, int CHALF>
__global__ void __launch_bounds__(256, 2)
gemm_tf32_kernel(const void* __restrict__ Av, const float* __restrict__ B,
                 const float* __restrict__ bias,
                 const float* __restrict__ asrc, const float* __restrict__ adst,
                 void* __restrict__ Cv, int M, int N, int K)
{
    const int BM = 128, BN = 128, BK = 32;
    const int APAD = 36;
    const int BPAD = 136;
    __shared__ unsigned As[BM * APAD];   // [m][k]
    __shared__ unsigned Bs[BK * BPAD];   // [k][n]

    const float*  Af = (const float*)Av;
    const __half* Ah = (const __half*)Av;
    float*  Cf = (float*)Cv;
    __half* Ch = (__half*)Cv;

    int tid = threadIdx.x;
    int wid = tid >> 5;
    int lane = tid & 31;
    int grp = lane >> 2;
    int tig = lane & 3;

    int warp_m = (wid & 3) * 32;
    int warp_n = (wid >> 2) * 64;

    int m0 = blockIdx.x * BM;
    int n0 = blockIdx.y * BN;

    float4 ra[4];
    uint4 rah[2];
    float4 rb[4];

    // prologue loads (k0 = 0)
    if (AHALF) {
#pragma unroll
        for (int j = 0; j < 2; j++) {
            int i = tid + j * 256;
            int row = i >> 2;
            int c8 = (i & 3) * 8;
            int gm = m0 + row;
            rah[j] = make_uint4(0u, 0u, 0u, 0u);
            if (gm < M) rah[j] = *(const uint4*)(Ah + (size_t)gm * K + c8);
        }
    } else {
#pragma unroll
        for (int j = 0; j < 4; j++) {
            int i = tid + j * 256;
            int row = i >> 3;
            int c4 = (i & 7) * 4;
            int gm = m0 + row;
            ra[j] = make_float4(0.f, 0.f, 0.f, 0.f);
            if (gm < M) ra[j] = *(const float4*)(Af + (size_t)gm * K + c4);
        }
    }
#pragma unroll
    for (int j = 0; j < 4; j++) {
        int i = tid + j * 256;
        int row = i >> 5;
        int c4 = (i & 31) * 4;
        rb[j] = *(const float4*)(B + (size_t)row * N + n0 + c4);
    }

    float acc[2][8][4];
#pragma unroll
    for (int i = 0; i < 2; i++)
#pragma unroll
        for (int j = 0; j < 8; j++)
#pragma unroll
            for (int q = 0; q < 4; q++) acc[i][j][q] = 0.0f;

    for (int k0 = 0; k0 < K; k0 += BK) {
        // store current tile (registers -> smem, tf32 convert)
        if (AHALF) {
#pragma unroll
            for (int j = 0; j < 2; j++) {
                int i = tid + j * 256;
                int row = i >> 2;
                int c8 = (i & 3) * 8;
                unsigned* p = &As[row * APAD + c8];
                const __half2* hv = (const __half2*)&rah[j];
#pragma unroll
                for (int q = 0; q < 4; q++) {
                    float2 f = __half22float2(hv[q]);
                    p[q * 2]     = f2tf32(f.x);
                    p[q * 2 + 1] = f2tf32(f.y);
                }
            }
        } else {
#pragma unroll
            for (int j = 0; j < 4; j++) {
                int i = tid + j * 256;
                int row = i >> 3;
                int c4 = (i & 7) * 4;
                unsigned* p = &As[row * APAD + c4];
                p[0] = f2tf32(ra[j].x); p[1] = f2tf32(ra[j].y);
                p[2] = f2tf32(ra[j].z); p[3] = f2tf32(ra[j].w);
            }
        }
#pragma unroll
        for (int j = 0; j < 4; j++) {
            int i = tid + j * 256;
            int row = i >> 5;
            int c4 = (i & 31) * 4;
            unsigned* p = &Bs[row * BPAD + c4];
            p[0] = f2tf32(rb[j].x); p[1] = f2tf32(rb[j].y);
            p[2] = f2tf32(rb[j].z); p[3] = f2tf32(rb[j].w);
        }
        __syncthreads();

        // prefetch next tile while computing
        int kn = k0 + BK;
        if (kn < K) {
            if (AHALF) {
#pragma unroll
                for (int j = 0; j < 2; j++) {
                    int i = tid + j * 256;
                    int row = i >> 2;
                    int c8 = (i & 3) * 8;
                    int gm = m0 + row;
                    rah[j] = make_uint4(0u, 0u, 0u, 0u);
                    if (gm < M) rah[j] = *(const uint4*)(Ah + (size_t)gm * K + kn + c8);
                }
            } else {
#pragma unroll
                for (int j = 0; j < 4; j++) {
                    int i = tid + j * 256;
                    int row = i >> 3;
                    int c4 = (i & 7) * 4;
                    int gm = m0 + row;
                    ra[j] = make_float4(0.f, 0.f, 0.f, 0.f);
                    if (gm < M) ra[j] = *(const float4*)(Af + (size_t)gm * K + kn + c4);
                }
            }
#pragma unroll
            for (int j = 0; j < 4; j++) {
                int i = tid + j * 256;
                int row = i >> 5;
                int c4 = (i & 31) * 4;
                rb[j] = *(const float4*)(B + (size_t)(kn + row) * N + n0 + c4);
            }
        }

#pragma unroll
        for (int kk = 0; kk < BK; kk += 8) {
            unsigned af[2][4];
#pragma unroll
            for (int mt = 0; mt < 2; mt++) {
                int r0 = warp_m + mt * 16 + grp;
                af[mt][0] = As[(r0)     * APAD + kk + tig];
                af[mt][1] = As[(r0 + 8) * APAD + kk + tig];
                af[mt][2] = As[(r0)     * APAD + kk + tig + 4];
                af[mt][3] = As[(r0 + 8) * APAD + kk + tig + 4];
            }
#pragma unroll
            for (int nt = 0; nt < 8; nt++) {
                int nb = warp_n + nt * 8 + grp;
                unsigned b0 = Bs[(kk + tig)     * BPAD + nb];
                unsigned b1 = Bs[(kk + tig + 4) * BPAD + nb];
#pragma unroll
                for (int mt = 0; mt < 2; mt++)
                    mma_tf32(acc[mt][nt][0], acc[mt][nt][1], acc[mt][nt][2], acc[mt][nt][3],
                             af[mt][0], af[mt][1], af[mt][2], af[mt][3], b0, b1);
            }
        }
        __syncthreads();
    }

    // --- epilogue ---
    int head = (n0 + warp_n) >> 6;   // warp tile spans exactly one head
#pragma unroll
    for (int mt = 0; mt < 2; mt++) {
#pragma unroll
        for (int half = 0; half < 2; half++) {
            int gm = m0 + warp_m + mt * 16 + grp + half * 8;
            if (gm >= M) continue;
            float ss = 0.0f, sd = 0.0f;
#pragma unroll
            for (int nt = 0; nt < 8; nt++) {
                int gn = n0 + warp_n + nt * 8 + tig * 2;
                float v0 = acc[mt][nt][half * 2 + 0];
                float v1 = acc[mt][nt][half * 2 + 1];
                if (EPI >= 1) { v0 += bias[gn]; v1 += bias[gn + 1]; }
                if (EPI == 1) { v0 = fmaxf(v0, 0.0f); v1 = fmaxf(v1, 0.0f); }
                if (SCORE) {
                    float2 a2 = *(const float2*)(asrc + gn);
                    float2 d2 = *(const float2*)(adst + gn);
                    ss += v0 * a2.x + v1 * a2.y;
                    sd += v0 * d2.x + v1 * d2.y;
                }
                if (CHALF) {
                    *(__half2*)(Ch + (size_t)gm * N + gn) = __floats2half2_rn(v0, v1);
                } else {
                    *(float2*)(Cf + (size_t)gm * N + gn) = make_float2(v0, v1);
                }
            }
            if (SCORE) {
                ss += __shfl_down_sync(0xffffffffu, ss, 2);
                ss += __shfl_down_sync(0xffffffffu, ss, 1);
                sd += __shfl_down_sync(0xffffffffu, sd, 2);
                sd += __shfl_down_sync(0xffffffffu, sd, 1);
                if (tig == 0) {
                    g_s_src[gm * HEADS + head] = ss;
                    g_s_dst[gm * HEADS + head] = sd;
                }
            }
        }
    }
}

// ---- gather kernel: one warp per dst node, CSR edges, fp16 h, fp32 accum ----
__global__ void gather_kernel() {
    int gw = (blockIdx.x * blockDim.x + threadIdx.x) >> 5;
    int lane = threadIdx.x & 31;
    if (gw >= NN) return;

    int beg = g_off[gw];
    int end = g_off[gw + 1];
    int head = lane >> 3;           // lane covers halves [lane*8, lane*8+8)

    float sdst = (lane < HEADS) ? g_s_dst[gw * HEADS + lane] : 0.0f;

    float acc[8];
#pragma unroll
    for (int q = 0; q < 8; q++) acc[q] = 0.0f;
    float den = 0.0f;

    for (int chunk = beg; chunk < end; chunk += 32) {
        int myE = (chunk + lane < end) ? g_esrc[chunk + lane] : 0;
        int cnt = min(32, end - chunk);
        for (int j = 0; j < cnt; j++) {
            int s = __shfl_sync(0xffffffffu, myE, j);
            float ex = 0.0f;
            if (lane < HEADS) {
                float e = g_s_src[s * HEADS + lane] + sdst;
                e = e > 0.0f ? e : 0.2f * e;
                ex = __expf(e);
                den += ex;
            }
            float exh = __shfl_sync(0xffffffffu, ex, head);
            uint4 v = ((const uint4*)(g_h + (size_t)s * HD))[lane];
            const __half2* hv = (const __half2*)&v;
#pragma unroll
            for (int q = 0; q < 4; q++) {
                float2 f = __half22float2(hv[q]);
                acc[q * 2]     = fmaf(exh, f.x, acc[q * 2]);
                acc[q * 2 + 1] = fmaf(exh, f.y, acc[q * 2 + 1]);
            }
        }
    }

    float denh = __shfl_sync(0xffffffffu, den, head);
    float inv = denh > 0.0f ? 1.0f / denh : 0.0f;

    uint4 outv;
    __half2* ov = (__half2*)&outv;
#pragma unroll
    for (int q = 0; q < 4; q++) {
        float x = fmaxf(acc[q * 2]     * inv, 0.0f);
        float y = fmaxf(acc[q * 2 + 1] * inv, 0.0f);
        ov[q] = __floats2half2_rn(x, y);
    }
    ((uint4*)(g_act + (size_t)gw * HD))[lane] = outv;
}

extern "C" void kernel_launch(void* const* d_in, const int* in_sizes, int n_in,
                              void* d_out, int out_size) {
    const float* node_emb = (const float*)d_in[0];
    const int*   src      = (const int*)d_in[1];
    const int*   dst      = (const int*)d_in[2];
    const float* W_n      = (const float*)d_in[3];
    const float* a_src    = (const float*)d_in[4];
    const float* a_dst    = (const float*)d_in[5];
    const float* W1       = (const float*)d_in[6];
    const float* b1       = (const float*)d_in[7];
    const float* W2       = (const float*)d_in[8];
    const float* b2       = (const float*)d_in[9];
    float* out = (float*)d_out;

    __half* h_ptr;   cudaGetSymbolAddress((void**)&h_ptr, g_h);
    __half* act_ptr; cudaGetSymbolAddress((void**)&act_ptr, g_act);
    __half* hid_ptr; cudaGetSymbolAddress((void**)&hid_ptr, g_hidden);
    float*  wc_ptr;  cudaGetSymbolAddress((void**)&wc_ptr, g_Wc);

    // 1. pack W + zero counts
    pack_w_kernel<<<(NN + 255) / 256, 256>>>(W_n);

    // 2. CSR-by-dst build
    hist_kernel<<<(NE + 255) / 256, 256>>>(dst);
    scan_blocks_kernel<<<NBLK, 1024>>>();
    scan_top_kernel<<<1, 64>>>();
    scan_final_kernel<<<NBLK, 1024>>>();
    scatter_kernel<<<(NE + 255) / 256, 256>>>(src, dst);

    // 3. GEMM1 + fused scores: h(fp16) = X @ Wc ; s_src/s_dst(fp32)
    {
        dim3 grid((NN + 127) / 128, HD / 128);
        gemm_tf32_kernel<0, 1, 0, 1><<<grid, 256>>>(node_emb, wc_ptr, nullptr,
                                                    a_src, a_dst, h_ptr, NN, HD, IND);
    }

    // 4. gather: per-dst softmax aggregation -> g_act (fp16, normalized + relu)
    gather_kernel<<<(NN * 32 + 255) / 256, 256>>>();

    // 5. GEMM2: hidden(fp16) = relu( act(fp16) @ W1 + b1 )
    {
        dim3 grid((NN + 127) / 128, HID / 128);
        gemm_tf32_kernel<1, 0, 1, 1><<<grid, 256>>>(act_ptr, W1, b1,
                                                    nullptr, nullptr, hid_ptr, NN, HID, HD);
    }

    // 6. GEMM3: out(fp32) = hidden(fp16) @ W2 + b2
    {
        dim3 grid((NN + 127) / 128, MOUT / 128);
        gemm_tf32_kernel<2, 0, 1, 0><<<grid, 256>>>(hid_ptr, W2, b2,
                                                    nullptr, nullptr, out, NN, MOUT, HID);
    }
}

// round 11
// speedup vs baseline: 2.4946x; 1.1292x over previous
#include <cuda_runtime.h>
#include <cuda_fp16.h>
#include <cuda_bf16.h>

#define NN 50000
#define NE 800000
#define IND 128
#define OUTD 64
#define HEADS 4
#define HD 256      // HEADS*OUTD
#define HID 256
#define MOUT 128
#define NBLK 49     // ceil(NN/1024)

// ---- scratch (device globals: allocation-free) ----
__device__ __half g_h[(size_t)NN * HD];       // transformed features (fp16)
__device__ __half g_act[(size_t)NN * HD];     // relu(num/den): GEMM2 input (fp16)
__device__ __half g_hidden[(size_t)NN * HID]; // MLP hidden (fp16)
__device__ float g_s_src[NN * HEADS];
__device__ float g_s_dst[NN * HEADS];
// weights: fp16, pre-transposed to [N][K] (col-major B for m16n8k16)
__device__ __half g_WcT[HD * IND];
__device__ __half g_W1T[HID * HD];
__device__ __half g_W2T[MOUT * HID];
// CSR-by-dst build
__device__ int g_cnt[NN];
__device__ int g_off[NN + 1];
__device__ int g_pos[NN];
__device__ int g_esrc[NE];
__device__ int g_ticket;
__device__ volatile int g_flag[NBLK];

// ---- pack weights (fp16, transposed) + reset counters/flags ----
__global__ void pack_w_kernel(const float* __restrict__ Wn,
                              const float* __restrict__ W1,
                              const float* __restrict__ W2) {
    int i = blockIdx.x * blockDim.x + threadIdx.x;
    if (i < HD * IND) {          // WcT[j][c] = Wn[h, c, d], j = h*64+d
        int j = i / IND;
        int c = i % IND;
        int h = j >> 6;
        int d = j & 63;
        g_WcT[i] = __float2half_rn(Wn[h * (IND * OUTD) + c * OUTD + d]);
    }
    if (i < HID * HD) {          // W1T[n][k] = W1[k][n]
        int n = i / HD;
        int k = i % HD;
        g_W1T[i] = __float2half_rn(W1[k * HID + n]);
    }
    if (i < MOUT * HID) {        // W2T[n][k] = W2[k][n]
        int n = i / HID;
        int k = i % HID;
        g_W2T[i] = __float2half_rn(W2[k * MOUT + n]);
    }
    if (i < NN) g_cnt[i] = 0;
    if (i < NBLK) g_flag[i] = 0;
    if (i == 0) g_ticket = 0;
}

// ---- histogram of dst ----
__global__ void hist_kernel(const int* __restrict__ dst) {
    int i = blockIdx.x * blockDim.x + threadIdx.x;
    if (i < NE) atomicAdd(&g_cnt[dst[i]], 1);
}

// ---- single-pass chained scan (decoupled lookback, ticket-ordered) ----
__global__ void scan_chain_kernel() {
    __shared__ int wsum[32];
    __shared__ int s_bid, s_prev;
    int tid = threadIdx.x;           // 1024
    int lane = tid & 31;
    int wid = tid >> 5;
    if (tid == 0) s_bid = atomicAdd(&g_ticket, 1);
    __syncthreads();
    int bid = s_bid;

    int i = bid * 1024 + tid;
    int v = (i < NN) ? g_cnt[i] : 0;
    int x = v;
#pragma unroll
    for (int o = 1; o < 32; o <<= 1) {
        int t = __shfl_up_sync(0xffffffffu, x, o);
        if (lane >= o) x += t;
    }
    if (lane == 31) wsum[wid] = x;
    __syncthreads();
    if (wid == 0) {
        int s = wsum[lane];
#pragma unroll
        for (int o = 1; o < 32; o <<= 1) {
            int t = __shfl_up_sync(0xffffffffu, s, o);
            if (lane >= o) s += t;
        }
        wsum[lane] = s;
    }
    __syncthreads();
    int incl = x + ((wid > 0) ? wsum[wid - 1] : 0);
    int total = wsum[31];

    if (tid == 0) {
        int prev = 0;
        if (bid > 0) {
            int f;
            do { f = g_flag[bid - 1]; } while (f == 0);
            prev = f - 1;                 // flag carries inclusive prefix + 1
        }
        g_flag[bid] = prev + total + 1;
        s_prev = prev;
    }
    __syncthreads();
    int excl = incl - v + s_prev;
    if (i < NN) { g_off[i] = excl; g_pos[i] = excl; }
    if (bid == NBLK - 1 && tid == 0) g_off[NN] = NE;
}

// ---- scatter edges into dst-grouped order ----
__global__ void scatter_kernel(const int* __restrict__ src, const int* __restrict__ dst) {
    int i = blockIdx.x * blockDim.x + threadIdx.x;
    if (i < NE) {
        int d = dst[i];
        int p = atomicAdd(&g_pos[d], 1);
        g_esrc[p] = src[i];
    }
}

__device__ __forceinline__ void mma_f16(float& c0, float& c1, float& c2, float& c3,
                                        unsigned a0, unsigned a1, unsigned a2, unsigned a3,
                                        unsigned b0, unsigned b1) {
    asm volatile("mma.sync.aligned.m16n8k16.row.col.f32.f16.f16.f32 "
                 "{%0,%1,%2,%3}, {%4,%5,%6,%7}, {%8,%9}, {%0,%1,%2,%3};"
                 : "+f"(c0), "+f"(c1), "+f"(c2), "+f"(c3)
                 : "r"(a0), "r"(a1), "r"(a2), "r"(a3), "r"(b0), "r"(b1));
}

// ---- fp16 tensor-core GEMM with register prefetch ----
// C[M,N] = act(A @ BT^T + bias). BT is fp16 [N][K] (pre-transposed).
// EPI 0: none. 1: +bias, relu. 2: +bias.
// SCORE 1: emit g_s_src/g_s_dst from fp32 accumulators (GEMM1 only).
// AHALF: A is fp16 (else fp32). CHALF: C is fp16 (else fp32).
template<int EPI, int SCORE, int AHALF, int CHALF>
__global__ void __launch_bounds__(256, 2)
gemm_f16_kernel(const void* __restrict__ Av, const __half* __restrict__ BT,
                const float* __restrict__ bias,
                const float* __restrict__ asrc, const float* __restrict__ adst,
                void* __restrict__ Cv, int M, int N, int K)
{
    const int BM = 128, BN = 128, BK = 32;
    const int PAD = 40;                 // halves per row (80B): conflict-free frag LDS
    __shared__ __half As[BM * PAD];     // [m][k]
    __shared__ __half Bs[BN * PAD];     // [n][k]

    const float*  Af = (const float*)Av;
    const __half* Ah = (const __half*)Av;
    float*  Cf = (float*)Cv;
    __half* Ch = (__half*)Cv;

    int tid = threadIdx.x;
    int wid = tid >> 5;
    int lane = tid & 31;
    int grp = lane >> 2;
    int tig = lane & 3;

    int warp_m = (wid & 3) * 32;
    int warp_n = (wid >> 2) * 64;

    int m0 = blockIdx.x * BM;
    int n0 = blockIdx.y * BN;

    float4 ra[4];
    uint4 rah[2];
    uint4 rb[2];

    // prologue loads (k0 = 0)
    if (AHALF) {
#pragma unroll
        for (int j = 0; j < 2; j++) {
            int i = tid + j * 256;
            int row = i >> 2;
            int c8 = (i & 3) * 8;
            int gm = m0 + row;
            rah[j] = make_uint4(0u, 0u, 0u, 0u);
            if (gm < M) rah[j] = *(const uint4*)(Ah + (size_t)gm * K + c8);
        }
    } else {
#pragma unroll
        for (int j = 0; j < 4; j++) {
            int i = tid + j * 256;
            int row = i >> 3;
            int c4 = (i & 7) * 4;
            int gm = m0 + row;
            ra[j] = make_float4(0.f, 0.f, 0.f, 0.f);
            if (gm < M) ra[j] = *(const float4*)(Af + (size_t)gm * K + c4);
        }
    }
#pragma unroll
    for (int j = 0; j < 2; j++) {
        int i = tid + j * 256;
        int n = i >> 2;
        int c8 = (i & 3) * 8;
        rb[j] = *(const uint4*)(BT + (size_t)(n0 + n) * K + c8);
    }

    float acc[2][8][4];
#pragma unroll
    for (int i = 0; i < 2; i++)
#pragma unroll
        for (int j = 0; j < 8; j++)
#pragma unroll
            for (int q = 0; q < 4; q++) acc[i][j][q] = 0.0f;

    for (int k0 = 0; k0 < K; k0 += BK) {
        // store current tile to smem
        if (AHALF) {
#pragma unroll
            for (int j = 0; j < 2; j++) {
                int i = tid + j * 256;
                int row = i >> 2;
                int c8 = (i & 3) * 8;
                *(uint4*)&As[row * PAD + c8] = rah[j];
            }
        } else {
#pragma unroll
            for (int j = 0; j < 4; j++) {
                int i = tid + j * 256;
                int row = i >> 3;
                int c4 = (i & 7) * 4;
                __half2* p = (__half2*)&As[row * PAD + c4];
                p[0] = __floats2half2_rn(ra[j].x, ra[j].y);
                p[1] = __floats2half2_rn(ra[j].z, ra[j].w);
            }
        }
#pragma unroll
        for (int j = 0; j < 2; j++) {
            int i = tid + j * 256;
            int n = i >> 2;
            int c8 = (i & 3) * 8;
            *(uint4*)&Bs[n * PAD + c8] = rb[j];
        }
        __syncthreads();

        // prefetch next tile while computing
        int kn = k0 + BK;
        if (kn < K) {
            if (AHALF) {
#pragma unroll
                for (int j = 0; j < 2; j++) {
                    int i = tid + j * 256;
                    int row = i >> 2;
                    int c8 = (i & 3) * 8;
                    int gm = m0 + row;
                    rah[j] = make_uint4(0u, 0u, 0u, 0u);
                    if (gm < M) rah[j] = *(const uint4*)(Ah + (size_t)gm * K + kn + c8);
                }
            } else {
#pragma unroll
                for (int j = 0; j < 4; j++) {
                    int i = tid + j * 256;
                    int row = i >> 3;
                    int c4 = (i & 7) * 4;
                    int gm = m0 + row;
                    ra[j] = make_float4(0.f, 0.f, 0.f, 0.f);
                    if (gm < M) ra[j] = *(const float4*)(Af + (size_t)gm * K + kn + c4);
                }
            }
#pragma unroll
            for (int j = 0; j < 2; j++) {
                int i = tid + j * 256;
                int n = i >> 2;
                int c8 = (i & 3) * 8;
                rb[j] = *(const uint4*)(BT + (size_t)(n0 + n) * K + kn + c8);
            }
        }

        // compute: 2 k-steps of m16n8k16
#pragma unroll
        for (int kk = 0; kk < BK; kk += 16) {
            unsigned af[2][4];
#pragma unroll
            for (int mt = 0; mt < 2; mt++) {
                int r0 = warp_m + mt * 16 + grp;
                af[mt][0] = *(const unsigned*)&As[(r0)     * PAD + kk + 2 * tig];
                af[mt][1] = *(const unsigned*)&As[(r0 + 8) * PAD + kk + 2 * tig];
                af[mt][2] = *(const unsigned*)&As[(r0)     * PAD + kk + 2 * tig + 8];
                af[mt][3] = *(const unsigned*)&As[(r0 + 8) * PAD + kk + 2 * tig + 8];
            }
#pragma unroll
            for (int nt = 0; nt < 8; nt++) {
                int nb = warp_n + nt * 8 + grp;
                unsigned b0 = *(const unsigned*)&Bs[nb * PAD + kk + 2 * tig];
                unsigned b1 = *(const unsigned*)&Bs[nb * PAD + kk + 2 * tig + 8];
#pragma unroll
                for (int mt = 0; mt < 2; mt++)
                    mma_f16(acc[mt][nt][0], acc[mt][nt][1], acc[mt][nt][2], acc[mt][nt][3],
                            af[mt][0], af[mt][1], af[mt][2], af[mt][3], b0, b1);
            }
        }
        __syncthreads();
    }

    // --- epilogue ---
    int head = (n0 + warp_n) >> 6;   // warp tile spans exactly one head
#pragma unroll
    for (int mt = 0; mt < 2; mt++) {
#pragma unroll
        for (int half = 0; half < 2; half++) {
            int gm = m0 + warp_m + mt * 16 + grp + half * 8;
            if (gm >= M) continue;
            float ss = 0.0f, sd = 0.0f;
#pragma unroll
            for (int nt = 0; nt < 8; nt++) {
                int gn = n0 + warp_n + nt * 8 + tig * 2;
                float v0 = acc[mt][nt][half * 2 + 0];
                float v1 = acc[mt][nt][half * 2 + 1];
                if (EPI >= 1) { v0 += bias[gn]; v1 += bias[gn + 1]; }
                if (EPI == 1) { v0 = fmaxf(v0, 0.0f); v1 = fmaxf(v1, 0.0f); }
                if (SCORE) {
                    float2 a2 = *(const float2*)(asrc + gn);
                    float2 d2 = *(const float2*)(adst + gn);
                    ss += v0 * a2.x + v1 * a2.y;
                    sd += v0 * d2.x + v1 * d2.y;
                }
                if (CHALF) {
                    *(__half2*)(Ch + (size_t)gm * N + gn) = __floats2half2_rn(v0, v1);
                } else {
                    *(float2*)(Cf + (size_t)gm * N + gn) = make_float2(v0, v1);
                }
            }
            if (SCORE) {
                ss += __shfl_down_sync(0xffffffffu, ss, 2);
                ss += __shfl_down_sync(0xffffffffu, ss, 1);
                sd += __shfl_down_sync(0xffffffffu, sd, 2);
                sd += __shfl_down_sync(0xffffffffu, sd, 1);
                if (tig == 0) {
                    g_s_src[gm * HEADS + head] = ss;
                    g_s_dst[gm * HEADS + head] = sd;
                }
            }
        }
    }
}

// ---- gather kernel: one warp per dst node, CSR edges, fp16 h, fp32 accum ----
__global__ void gather_kernel() {
    int gw = (blockIdx.x * blockDim.x + threadIdx.x) >> 5;
    int lane = threadIdx.x & 31;
    if (gw >= NN) return;

    int beg = g_off[gw];
    int end = g_off[gw + 1];
    int head = lane >> 3;           // lane covers halves [lane*8, lane*8+8)

    float sdst = (lane < HEADS) ? g_s_dst[gw * HEADS + lane] : 0.0f;

    float acc[8];
#pragma unroll
    for (int q = 0; q < 8; q++) acc[q] = 0.0f;
    float den = 0.0f;

    for (int chunk = beg; chunk < end; chunk += 32) {
        int myE = (chunk + lane < end) ? g_esrc[chunk + lane] : 0;
        int cnt = min(32, end - chunk);
        for (int j = 0; j < cnt; j++) {
            int s = __shfl_sync(0xffffffffu, myE, j);
            float ex = 0.0f;
            if (lane < HEADS) {
                float e = g_s_src[s * HEADS + lane] + sdst;
                e = e > 0.0f ? e : 0.2f * e;
                ex = __expf(e);
                den += ex;
            }
            float exh = __shfl_sync(0xffffffffu, ex, head);
            uint4 v = ((const uint4*)(g_h + (size_t)s * HD))[lane];
            const __half2* hv = (const __half2*)&v;
#pragma unroll
            for (int q = 0; q < 4; q++) {
                float2 f = __half22float2(hv[q]);
                acc[q * 2]     = fmaf(exh, f.x, acc[q * 2]);
                acc[q * 2 + 1] = fmaf(exh, f.y, acc[q * 2 + 1]);
            }
        }
    }

    float denh = __shfl_sync(0xffffffffu, den, head);
    float inv = denh > 0.0f ? 1.0f / denh : 0.0f;

    uint4 outv;
    __half2* ov = (__half2*)&outv;
#pragma unroll
    for (int q = 0; q < 4; q++) {
        float x = fmaxf(acc[q * 2]     * inv, 0.0f);
        float y = fmaxf(acc[q * 2 + 1] * inv, 0.0f);
        ov[q] = __floats2half2_rn(x, y);
    }
    ((uint4*)(g_act + (size_t)gw * HD))[lane] = outv;
}

extern "C" void kernel_launch(void* const* d_in, const int* in_sizes, int n_in,
                              void* d_out, int out_size) {
    const float* node_emb = (const float*)d_in[0];
    const int*   src      = (const int*)d_in[1];
    const int*   dst      = (const int*)d_in[2];
    const float* W_n      = (const float*)d_in[3];
    const float* a_src    = (const float*)d_in[4];
    const float* a_dst    = (const float*)d_in[5];
    const float* W1       = (const float*)d_in[6];
    const float* b1       = (const float*)d_in[7];
    const float* W2       = (const float*)d_in[8];
    const float* b2       = (const float*)d_in[9];
    float* out = (float*)d_out;

    __half* h_ptr;   cudaGetSymbolAddress((void**)&h_ptr, g_h);
    __half* act_ptr; cudaGetSymbolAddress((void**)&act_ptr, g_act);
    __half* hid_ptr; cudaGetSymbolAddress((void**)&hid_ptr, g_hidden);
    __half* wcT_ptr; cudaGetSymbolAddress((void**)&wcT_ptr, g_WcT);
    __half* w1T_ptr; cudaGetSymbolAddress((void**)&w1T_ptr, g_W1T);
    __half* w2T_ptr; cudaGetSymbolAddress((void**)&w2T_ptr, g_W2T);

    // 1. pack weights (fp16 transposed) + reset counters
    pack_w_kernel<<<(HID * HD + 255) / 256, 256>>>(W_n, W1, W2);

    // 2. CSR-by-dst build
    hist_kernel<<<(NE + 255) / 256, 256>>>(dst);
    scan_chain_kernel<<<NBLK, 1024>>>();
    scatter_kernel<<<(NE + 255) / 256, 256>>>(src, dst);

    // 3. GEMM1 + fused scores: h(fp16) = X @ Wc ; s_src/s_dst(fp32)
    {
        dim3 grid((NN + 127) / 128, HD / 128);
        gemm_f16_kernel<0, 1, 0, 1><<<grid, 256>>>(node_emb, wcT_ptr, nullptr,
                                                   a_src, a_dst, h_ptr, NN, HD, IND);
    }

    // 4. gather: per-dst softmax aggregation -> g_act (fp16, normalized + relu)
    gather_kernel<<<(NN * 32 + 255) / 256, 256>>>();

    // 5. GEMM2: hidden(fp16) = relu( act(fp16) @ W1 + b1 )
    {
        dim3 grid((NN + 127) / 128, HID / 128);
        gemm_f16_kernel<1, 0, 1, 1><<<grid, 256>>>(act_ptr, w1T_ptr, b1,
                                                   nullptr, nullptr, hid_ptr, NN, HID, HD);
    }

    // 6. GEMM3: out(fp32) = hidden(fp16) @ W2 + b2
    {
        dim3 grid((NN + 127) / 128, MOUT / 128);
        gemm_f16_kernel<2, 0, 1, 0><<<grid, 256>>>(hid_ptr, w2T_ptr, b2,
                                                   nullptr, nullptr, out, NN, MOUT, HID);
    }
}